// round 7
// baseline (speedup 1.0000x reference)
#include <cuda_runtime.h>
#include <cuda_fp16.h>
#include <cuda_bf16.h>

// GAT encoder. Structural constants: EMB=32, H=4, C=32 -> HC=128.
// Runtime shapes: GN=|x|, E=|adj|/2, N=|emb_table|/32, G=GN/N.

#define HC 128
#define EMB 32
#define MAX_N   8192
#define MAXDEG  96      // fixed-stride edge buckets per dst (deg~Poisson(16))

// Per-TOKEN tables (hl depends only on token id):
__device__ __half g_HLh[(size_t)MAX_N * HC];   // [N,128] fp16
__device__ float  g_AS[MAX_N * 4];             // per-token src logits (fp32)
__device__ float  g_AD[MAX_N * 4];             // per-token dst logits (fp32)
__device__ int    g_deg[MAX_N];                // zero at entry; last k_agg block re-zeroes
__device__ int    g_col[MAX_N * MAXDEG];       // bucketed src lists (no self loops)
__device__ int    g_done;                      // ticket counter for last-block reset

// ---------------- launch 0: fused edge-bucket scatter + per-token features ----
// Blocks [0, SCB): scatter edges into per-dst buckets.
// Blocks [SCB, SCB+TKB): warp-per-(token,head) linear transform + logits.

#define TKB 128   // token blocks (256 thr = 8 warps each)

__global__ __launch_bounds__(256) void k_fused(const int* __restrict__ adj, int E,
                                               const float* __restrict__ emb,
                                               const float* __restrict__ lin_w,
                                               const float* __restrict__ att_src,
                                               const float* __restrict__ att_dst,
                                               int N, int SCB) {
    if ((int)blockIdx.x < SCB) {
        int e = blockIdx.x * 256 + threadIdx.x;
        if (e < E) {
            int s = adj[e];
            int d = adj[E + e];
            int pos = atomicAdd(&g_deg[d], 1);
            if (pos < MAXDEG) g_col[d * MAXDEG + pos] = s;
        }
        return;
    }
    // token part: warp per (token, head)
    int bi = (int)blockIdx.x - SCB;
    int w = threadIdx.x >> 5, lane = threadIdx.x & 31;
    int wg = bi * 8 + w;
    int head = wg & 3;
    int tok0 = wg >> 2;
    int tstride = TKB * 2;

    float wreg[EMB];
    int colidx = head * 32 + lane;
    #pragma unroll
    for (int k = 0; k < EMB; k++) wreg[k] = __ldg(&lin_w[k * HC + colidx]);
    float as_t = __ldg(&att_src[colidx]);
    float ad_t = __ldg(&att_dst[colidx]);

    for (int tok = tok0; tok < N; tok += tstride) {
        float ev = __ldg(&emb[(size_t)tok * EMB + lane]);
        float acc = 0.f;
        #pragma unroll
        for (int k = 0; k < EMB; k++)
            acc = fmaf(__shfl_sync(0xffffffffu, ev, k), wreg[k], acc);
        g_HLh[(size_t)tok * HC + colidx] = __float2half_rn(acc);
        float ps = acc * as_t, pd = acc * ad_t;
        #pragma unroll
        for (int o = 16; o > 0; o >>= 1) {
            ps += __shfl_down_sync(0xffffffffu, ps, o);
            pd += __shfl_down_sync(0xffffffffu, pd, o);
        }
        if (lane == 0) {
            g_AS[tok * 4 + head] = ps;
            g_AD[tok * 4 + head] = pd;
        }
    }
}

// ---------------- launch 1: aggregation, warp per (g,dst) row ----------------
// Lane owns 4 consecutive output columns; head h = lane>>3.
// Self loop handled analytically. Softmax reduction deferred past the gather.
// g_deg reset is done ONLY by the last-finishing block (ticket), so no block
// zeroes a counter another block still needs to read.

#define WPB 8      // warps (rows) per block
#define CAP 48     // edges cached in smem per warp

__device__ __forceinline__ float4 h4_to_f4(uint2 u) {
    float2 fa = __half22float2(*(__half2*)&u.x);
    float2 fb = __half22float2(*(__half2*)&u.y);
    return make_float4(fa.x, fa.y, fb.x, fb.y);
}

__global__ __launch_bounds__(WPB * 32) void k_agg(const int* __restrict__ x,
                                                  const float* __restrict__ bias,
                                                  float* __restrict__ out,
                                                  int N, int G) {
    __shared__ float s_ex[WPB][CAP * 4];
    __shared__ int   s_tok[WPB][CAP];
    __shared__ int   s_last;

    int w = threadIdx.x >> 5, lane = threadIdx.x & 31;
    int row = blockIdx.x * WPB + w;
    int g = row / N, n = row - g * N;
    bool active = (row < G * N);

    if (active) {
        const int* xg = x + (size_t)g * N;

        int deg = g_deg[n];
        if (deg > MAXDEG) deg = MAXDEG;
        int rs = n * MAXDEG;
        int h = lane >> 3;

        int dtok = __ldg(&xg[n]);
        float4 ad  = *(const float4*)&g_AD[dtok * 4];
        float4 asd = *(const float4*)&g_AS[dtok * 4];

        // self-loop exp term
        float4 eself;
        {
            float vx = asd.x + ad.x, vy = asd.y + ad.y, vz = asd.z + ad.z, vw = asd.w + ad.w;
            vx = vx > 0.f ? vx : 0.2f * vx;
            vy = vy > 0.f ? vy : 0.2f * vy;
            vz = vz > 0.f ? vz : 0.2f * vz;
            vw = vw > 0.f ? vw : 0.2f * vw;
            eself = make_float4(__expf(vx), __expf(vy), __expf(vz), __expf(vw));
        }

        // phase 1: per-edge exp(leaky_relu(logit)) -> smem; partial sums in regs
        float4 sum = make_float4(0.f, 0.f, 0.f, 0.f);
        if (lane == 0) sum = eself;
        int nch = (deg + 31) >> 5;
        for (int c = 0; c < nch; c++) {
            int i = c * 32 + lane;
            if (i < deg) {
                int tok = __ldg(&xg[g_col[rs + i]]);
                float4 as = *(const float4*)&g_AS[tok * 4];
                float vx = as.x + ad.x, vy = as.y + ad.y, vz = as.z + ad.z, vw = as.w + ad.w;
                vx = vx > 0.f ? vx : 0.2f * vx;
                vy = vy > 0.f ? vy : 0.2f * vy;
                vz = vz > 0.f ? vz : 0.2f * vz;
                vw = vw > 0.f ? vw : 0.2f * vw;
                float4 e4 = make_float4(__expf(vx), __expf(vy), __expf(vz), __expf(vw));
                sum.x += e4.x; sum.y += e4.y; sum.z += e4.z; sum.w += e4.w;
                if (i < CAP) {
                    s_tok[w][i] = tok;
                    float* d = &s_ex[w][i * 4];
                    d[0] = e4.x; d[1] = e4.y; d[2] = e4.z; d[3] = e4.w;
                }
            }
        }
        __syncwarp();

        // phase 2: gather fp16 HL rows weighted by exp (unnormalized), MLP=8
        float alself = (h == 0) ? eself.x : (h == 1) ? eself.y : (h == 2) ? eself.z : eself.w;
        const uint2* HLv = (const uint2*)g_HLh;
        float4 acc;
        {
            float4 v = h4_to_f4(__ldg(&HLv[(size_t)dtok * 32 + lane]));
            acc = make_float4(alself * v.x, alself * v.y, alself * v.z, alself * v.w);
        }
        int cached = deg < CAP ? deg : CAP;
        int e = 0;
        for (; e + 7 < cached; e += 8) {
            uint2 u[8]; float a[8];
            #pragma unroll
            for (int j = 0; j < 8; j++) {
                int tk = s_tok[w][e + j];
                a[j] = s_ex[w][(e + j) * 4 + h];
                u[j] = __ldg(&HLv[(size_t)tk * 32 + lane]);
            }
            #pragma unroll
            for (int j = 0; j < 8; j++) {
                float4 v = h4_to_f4(u[j]);
                acc.x = fmaf(a[j], v.x, acc.x); acc.y = fmaf(a[j], v.y, acc.y);
                acc.z = fmaf(a[j], v.z, acc.z); acc.w = fmaf(a[j], v.w, acc.w);
            }
        }
        for (; e + 3 < cached; e += 4) {
            uint2 u[4]; float a[4];
            #pragma unroll
            for (int j = 0; j < 4; j++) {
                int tk = s_tok[w][e + j];
                a[j] = s_ex[w][(e + j) * 4 + h];
                u[j] = __ldg(&HLv[(size_t)tk * 32 + lane]);
            }
            #pragma unroll
            for (int j = 0; j < 4; j++) {
                float4 v = h4_to_f4(u[j]);
                acc.x = fmaf(a[j], v.x, acc.x); acc.y = fmaf(a[j], v.y, acc.y);
                acc.z = fmaf(a[j], v.z, acc.z); acc.w = fmaf(a[j], v.w, acc.w);
            }
        }
        for (; e < cached; e++) {
            int tk = s_tok[w][e];
            float al = s_ex[w][e * 4 + h];
            float4 v = h4_to_f4(__ldg(&HLv[(size_t)tk * 32 + lane]));
            acc.x = fmaf(al, v.x, acc.x); acc.y = fmaf(al, v.y, acc.y);
            acc.z = fmaf(al, v.z, acc.z); acc.w = fmaf(al, v.w, acc.w);
        }
        float adh = (h == 0) ? ad.x : (h == 1) ? ad.y : (h == 2) ? ad.z : ad.w;
        for (e = cached; e < deg; e++) {   // rare overflow path (deg > CAP)
            int tok = __ldg(&xg[g_col[rs + e]]);
            float v = g_AS[tok * 4 + h] + adh;
            v = v > 0.f ? v : 0.2f * v;
            float al = __expf(v);
            float4 hv = h4_to_f4(__ldg(&HLv[(size_t)tok * 32 + lane]));
            acc.x = fmaf(al, hv.x, acc.x); acc.y = fmaf(al, hv.y, acc.y);
            acc.z = fmaf(al, hv.z, acc.z); acc.w = fmaf(al, hv.w, acc.w);
        }

        // deferred softmax reduction
        #pragma unroll
        for (int o = 16; o > 0; o >>= 1) {
            sum.x += __shfl_xor_sync(0xffffffffu, sum.x, o);
            sum.y += __shfl_xor_sync(0xffffffffu, sum.y, o);
            sum.z += __shfl_xor_sync(0xffffffffu, sum.z, o);
            sum.w += __shfl_xor_sync(0xffffffffu, sum.w, o);
        }
        float den = (h == 0) ? sum.x : (h == 1) ? sum.y : (h == 2) ? sum.z : sum.w;
        float inv = 1.f / den;

        const float4* b4 = (const float4*)bias;
        float4 bb = __ldg(&b4[lane]);
        float4 o4;
        o4.x = acc.x * inv + bb.x;
        o4.y = acc.y * inv + bb.y;
        o4.z = acc.z * inv + bb.z;
        o4.w = acc.w * inv + bb.w;
        ((float4*)out)[(size_t)row * 32 + lane] = o4;
    }

    // last-finishing block resets g_deg for the next graph replay
    __syncthreads();
    if (threadIdx.x == 0) {
        __threadfence();
        s_last = (atomicAdd(&g_done, 1) == (int)gridDim.x - 1);
    }
    __syncthreads();
    if (s_last) {
        for (int i = threadIdx.x; i < N; i += blockDim.x) g_deg[i] = 0;
        if (threadIdx.x == 0) g_done = 0;
    }
}

// ---------------- launch ----------------

extern "C" void kernel_launch(void* const* d_in, const int* in_sizes, int n_in,
                              void* d_out, int out_size) {
    const int*   x       = (const int*)  d_in[0];   // [G*N]
    const int*   adj     = (const int*)  d_in[1];   // [2,E]
    const float* emb     = (const float*)d_in[2];   // [N,32]
    const float* lin_w   = (const float*)d_in[3];   // [32,128]
    const float* att_src = (const float*)d_in[4];   // [128]
    const float* att_dst = (const float*)d_in[5];   // [128]
    const float* bias    = (const float*)d_in[6];   // [128]
    float* out = (float*)d_out;

    int GN = in_sizes[0];
    int E  = in_sizes[1] / 2;
    int N  = in_sizes[2] / EMB;
    int G  = GN / N;

    int SCB = (E + 255) / 256;
    k_fused<<<SCB + TKB, 256>>>(adj, E, emb, lin_w, att_src, att_dst, N, SCB);
    k_agg<<<(GN + WPB - 1) / WPB, WPB * 32>>>(x, bias, out, N, G);
    (void)n_in; (void)out_size;
}